// round 3
// baseline (speedup 1.0000x reference)
#include <cuda_runtime.h>

// L1LossWithPenalty: out = (1/N) * sum_i [ sum_c |pred[i,c]-tgt[i,c]| ] * penalty[argmax_c pred[i,:], argmax_c tgt[i,:]]
// N = 1048576, C = 27. Pure HBM-streaming reduction (226 MB read).
//
// Strategy:
//  - Block handles 128 rows. Stage both 128x27 tiles into shared via coalesced
//    float4 loads (chunk base = blockIdx*13824 B, 16B-aligned).
//  - One thread per row reads its 27 values from shared (stride 27, gcd(27,32)=1
//    -> bank-conflict-free), computes L1 sum + both argmaxes, looks up penalty
//    from a shared copy of the 27x27 table.
//  - Warp shuffle + shared reduce to one block partial; atomicAdd into a
//    __device__ double accumulator (8192 atomics, negligible).
//  - Tiny init kernel zeroes the accumulator; tiny finalize kernel writes
//    float(acc/N) to d_out. All three launches are graph-capturable, no allocs.

#define C 27
#define ROWS_PER_BLOCK 128
#define THREADS 128

__device__ double g_acc;

__global__ void init_kernel() {
    g_acc = 0.0;
}

__global__ __launch_bounds__(THREADS)
void l1pen_kernel(const float* __restrict__ pred,
                  const float* __restrict__ tgt,
                  const float* __restrict__ pen,
                  int nrows)
{
    __shared__ float s_pred[ROWS_PER_BLOCK * C];   // 13824 B
    __shared__ float s_tgt [ROWS_PER_BLOCK * C];   // 13824 B
    __shared__ float s_pen [C * C];                // 2916 B
    __shared__ float s_warp[THREADS / 32];

    const int tid = threadIdx.x;

    // Stage penalty table (729 floats).
    for (int i = tid; i < C * C; i += THREADS)
        s_pen[i] = pen[i];

    const int  row0 = blockIdx.x * ROWS_PER_BLOCK;
    const int  rows = min(ROWS_PER_BLOCK, nrows - row0);
    const long base = (long)row0 * C;
    const int  nflt = rows * C;

    // Coalesced float4 staging. base*4 bytes = blockIdx*13824, 16B-aligned.
    const float4* __restrict__ p4 = (const float4*)(pred + base);
    const float4* __restrict__ t4 = (const float4*)(tgt  + base);
    float4* sp4 = (float4*)s_pred;
    float4* st4 = (float4*)s_tgt;
    const int n4 = nflt >> 2;
    for (int i = tid; i < n4; i += THREADS) {
        sp4[i] = p4[i];
        st4[i] = t4[i];
    }
    // Scalar tail (only possible on a ragged last block).
    for (int i = (n4 << 2) + tid; i < nflt; i += THREADS) {
        s_pred[i] = pred[base + i];
        s_tgt [i] = tgt [base + i];
    }
    __syncthreads();

    // One thread per row: L1 sum + argmax(pred) + argmax(tgt) + penalty gather.
    float partial = 0.0f;
    if (tid < rows) {
        const float* __restrict__ pr = s_pred + tid * C;
        const float* __restrict__ tr = s_tgt  + tid * C;
        float l1 = 0.0f;
        float pmax = pr[0], tmax = tr[0];
        int   pidx = 0,     tidx = 0;
        #pragma unroll
        for (int c = 0; c < C; c++) {
            float a = pr[c];
            float b = tr[c];
            l1 += fabsf(a - b);
            if (a > pmax) { pmax = a; pidx = c; }   // strict > keeps first-max (jnp.argmax ties)
            if (b > tmax) { tmax = b; tidx = c; }
        }
        partial = l1 * s_pen[pidx * C + tidx];
    }

    // Warp reduce.
    #pragma unroll
    for (int off = 16; off > 0; off >>= 1)
        partial += __shfl_down_sync(0xffffffffu, partial, off);
    if ((tid & 31) == 0)
        s_warp[tid >> 5] = partial;
    __syncthreads();

    if (tid == 0) {
        float s = 0.0f;
        #pragma unroll
        for (int w = 0; w < THREADS / 32; w++)
            s += s_warp[w];
        atomicAdd(&g_acc, (double)s);
    }
}

__global__ void final_kernel(float* __restrict__ out, float invN) {
    *out = (float)g_acc * invN;
}

extern "C" void kernel_launch(void* const* d_in, const int* in_sizes, int n_in,
                              void* d_out, int out_size)
{
    // Identify penalty robustly by its element count (27*27=729); the two
    // [N,27] tensors keep their metadata order: predicted first, target second.
    int pen_i = -1;
    for (int i = 0; i < n_in; i++)
        if (in_sizes[i] == C * C) { pen_i = i; break; }
    int big[2], nb = 0;
    for (int i = 0; i < n_in && nb < 2; i++)
        if (i != pen_i) big[nb++] = i;

    const float* pred = (const float*)d_in[big[0]];
    const float* tgt  = (const float*)d_in[big[1]];
    const float* pen  = (const float*)d_in[pen_i];

    const int nrows = in_sizes[big[0]] / C;
    const int blocks = (nrows + ROWS_PER_BLOCK - 1) / ROWS_PER_BLOCK;

    init_kernel<<<1, 1>>>();
    l1pen_kernel<<<blocks, THREADS>>>(pred, tgt, pen, nrows);
    final_kernel<<<1, 1>>>((float*)d_out, 1.0f / (float)nrows);
}

// round 4
// speedup vs baseline: 1.0455x; 1.0455x over previous
#include <cuda_runtime.h>

// L1LossWithPenalty, single-kernel version.
// out = (1/N) * sum_i [ sum_c |pred[i,c]-tgt[i,c]| ] * penalty[argmax pred_i, argmax tgt_i]
// N = 1048576, C = 27.  226 MB streamed -> pure HBM-bound reduction.
//
// R3 changes vs R2 (59.6us):
//  - init/final kernels folded in: last block (atomic counter) writes d_out and
//    self-resets the device accumulators -> graph-replay-safe, saves ~8us of
//    launch overhead (init_kernel alone measured 4.06us in ncu).
//  - staging fully unrolled: 6 unconditional + 1 predicated float4 load per
//    array per thread, register-batched -> ~14 LDG.128 in flight (MLP ~14).

#define C        27
#define ROWS     128
#define THREADS  128
#define N4       ((ROWS * C) / 4)        // 864 float4 per array per tile
#define FULLIT   (N4 / THREADS)          // 6
#define REM      (N4 - FULLIT * THREADS) // 96

__device__ double   g_acc;    // zero at module load; self-reset each run
__device__ unsigned g_count;  // idem

__global__ __launch_bounds__(THREADS)
void l1pen_kernel(const float* __restrict__ pred,
                  const float* __restrict__ tgt,
                  const float* __restrict__ pen,
                  int nrows,
                  float* __restrict__ out)
{
    __shared__ float s_pred[ROWS * C];   // 13824 B
    __shared__ float s_tgt [ROWS * C];   // 13824 B
    __shared__ float s_pen [C * C];      // 2916 B
    __shared__ float s_warp[THREADS / 32];

    const int tid  = threadIdx.x;
    const int row0 = blockIdx.x * ROWS;
    const int rows = min(ROWS, nrows - row0);
    const long base = (long)row0 * C;

    // Penalty table to shared (729 floats).
    for (int i = tid; i < C * C; i += THREADS)
        s_pen[i] = pen[i];

    if (rows == ROWS) {
        // Fast path: fully unrolled, register-batched staging.
        // base bytes = blockIdx * 13824 -> 16B-aligned.
        const float4* __restrict__ p4 = (const float4*)(pred + base);
        const float4* __restrict__ t4 = (const float4*)(tgt  + base);
        float4 rp[FULLIT + 1], rt[FULLIT + 1];
        #pragma unroll
        for (int k = 0; k < FULLIT; k++) {
            rp[k] = p4[tid + k * THREADS];
            rt[k] = t4[tid + k * THREADS];
        }
        const bool extra = (tid < REM);
        if (extra) {
            rp[FULLIT] = p4[FULLIT * THREADS + tid];
            rt[FULLIT] = t4[FULLIT * THREADS + tid];
        }
        float4* sp4 = (float4*)s_pred;
        float4* st4 = (float4*)s_tgt;
        #pragma unroll
        for (int k = 0; k < FULLIT; k++) {
            sp4[tid + k * THREADS] = rp[k];
            st4[tid + k * THREADS] = rt[k];
        }
        if (extra) {
            sp4[FULLIT * THREADS + tid] = rp[FULLIT];
            st4[FULLIT * THREADS + tid] = rt[FULLIT];
        }
    } else {
        // Ragged last tile (not hit for N = 1M, which is 8192 full tiles).
        const int nflt = rows * C;
        for (int i = tid; i < nflt; i += THREADS) {
            s_pred[i] = pred[base + i];
            s_tgt [i] = tgt [base + i];
        }
    }
    __syncthreads();

    // One thread per row: L1 sum + both argmaxes + penalty gather.
    // Stride-27 shared reads: gcd(27,32)=1 -> conflict-free.
    float partial = 0.0f;
    if (tid < rows) {
        const float* __restrict__ pr = s_pred + tid * C;
        const float* __restrict__ tr = s_tgt  + tid * C;
        float l1 = 0.0f;
        float pmax = pr[0], tmax = tr[0];
        int   pidx = 0,     tidx = 0;
        #pragma unroll
        for (int c = 0; c < C; c++) {
            float a = pr[c];
            float b = tr[c];
            l1 += fabsf(a - b);
            if (a > pmax) { pmax = a; pidx = c; }  // strict > == jnp.argmax tie rule
            if (b > tmax) { tmax = b; tidx = c; }
        }
        partial = l1 * s_pen[pidx * C + tidx];
    }

    // Warp reduce, then cross-warp via shared.
    #pragma unroll
    for (int off = 16; off > 0; off >>= 1)
        partial += __shfl_down_sync(0xffffffffu, partial, off);
    if ((tid & 31) == 0)
        s_warp[tid >> 5] = partial;
    __syncthreads();

    if (tid == 0) {
        float s = 0.0f;
        #pragma unroll
        for (int w = 0; w < THREADS / 32; w++)
            s += s_warp[w];

        atomicAdd(&g_acc, (double)s);
        __threadfence();
        unsigned done = atomicAdd(&g_count, 1u) + 1u;
        if (done == gridDim.x) {
            // Last block: all partials are in (counter proves it, fence orders it).
            __threadfence();
            double v = atomicAdd(&g_acc, 0.0);   // coherent L2 read
            *out = (float)(v / (double)nrows);
            // Self-reset for the next graph replay (no concurrent writers now).
            g_acc   = 0.0;
            __threadfence();
            g_count = 0u;
        }
    }
}

extern "C" void kernel_launch(void* const* d_in, const int* in_sizes, int n_in,
                              void* d_out, int out_size)
{
    // Penalty identified by element count (27*27=729); big tensors keep
    // metadata order: predicted, then target.
    int pen_i = -1;
    for (int i = 0; i < n_in; i++)
        if (in_sizes[i] == C * C) { pen_i = i; break; }
    int big[2], nb = 0;
    for (int i = 0; i < n_in && nb < 2; i++)
        if (i != pen_i) big[nb++] = i;

    const float* pred = (const float*)d_in[big[0]];
    const float* tgt  = (const float*)d_in[big[1]];
    const float* pen  = (const float*)d_in[pen_i];

    const int nrows  = in_sizes[big[0]] / C;
    const int blocks = (nrows + ROWS - 1) / ROWS;

    l1pen_kernel<<<blocks, THREADS>>>(pred, tgt, pen, nrows, (float*)d_out);
}

// round 6
// speedup vs baseline: 1.2649x; 1.2099x over previous
#include <cuda_runtime.h>

// L1LossWithPenalty — cp.async double-buffered pipelined version (R5 = R4 resubmit;
// R4 bench died to a container/infra failure with no kernel signal).
// out = (1/N) * sum_i [ sum_c |pred[i,c]-tgt[i,c]| ] * penalty[argmax pred_i, argmax tgt_i]
// N = 1048576, C = 27.  226 MB streamed -> HBM-bound.
//
// Design vs R3 (57.0us, DRAM 48.6%, occ 36.4%):
//  - cp.async.cg global->shared, DOUBLE-BUFFERED: next tile's copies are in
//    flight while computing the current tile -> DRAM requests continuously
//    outstanding instead of burst/idle alternation.
//  - penalty table via __ldg (L1-resident 2.9KB) instead of smem -> smem is
//    55.3KB -> 4 blocks/SM.
//  - persistent blocks (grid=592), ~14 tiles each; ONE reduction + ONE double
//    atomic per block instead of per tile.

#define C        27
#define ROWS     128
#define THREADS  128
#define TILE_F   (ROWS * C)          // 3456 floats per array per tile
#define TILE_4   (TILE_F / 4)        // 864 float4
#define FULLIT   (TILE_4 / THREADS)  // 6
#define REM      (TILE_4 - FULLIT * THREADS) // 96
#define SMEM_BYTES (4 * TILE_F * 4)  // 2 buffers x (pred+tgt) = 55296 B
#define GRID     592                 // ~4 blocks/SM on 148 SMs

__device__ double   g_acc;    // zero at module load; self-reset each run
__device__ unsigned g_count;

__device__ __forceinline__ void cp16(float* smem_dst, const float4* gmem_src) {
    unsigned saddr = (unsigned)__cvta_generic_to_shared(smem_dst);
    asm volatile("cp.async.cg.shared.global [%0], [%1], 16;\n"
                 :: "r"(saddr), "l"(gmem_src) : "memory");
}
__device__ __forceinline__ void cp_commit() {
    asm volatile("cp.async.commit_group;\n" ::: "memory");
}
__device__ __forceinline__ void cp_wait1() {
    asm volatile("cp.async.wait_group 1;\n" ::: "memory");
}

__global__ __launch_bounds__(THREADS)
void l1pen_kernel(const float* __restrict__ pred,
                  const float* __restrict__ tgt,
                  const float* __restrict__ pen,
                  int nrows,
                  float* __restrict__ out)
{
    extern __shared__ float dynsm[];
    // layout: [buf][array][TILE_F]  -> buf*2*TILE_F + array*TILE_F
    __shared__ float s_warp[THREADS / 32];

    const int tid    = threadIdx.x;
    const int ntiles = (nrows + ROWS - 1) / ROWS;
    const int stride = gridDim.x;

    // ---- issue copies for one tile into buffer b ----
    auto issue_tile = [&](int tile, int b) {
        float* sp = dynsm + b * 2 * TILE_F;
        float* st = sp + TILE_F;
        const long base = (long)tile * TILE_F;
        const int rows = min(ROWS, nrows - tile * ROWS);
        if (rows == ROWS) {
            const float4* p4 = (const float4*)(pred + base);
            const float4* t4 = (const float4*)(tgt  + base);
            #pragma unroll
            for (int k = 0; k < FULLIT; k++) {
                cp16(sp + (tid + k * THREADS) * 4, p4 + tid + k * THREADS);
                cp16(st + (tid + k * THREADS) * 4, t4 + tid + k * THREADS);
            }
            if (tid < REM) {
                cp16(sp + (FULLIT * THREADS + tid) * 4, p4 + FULLIT * THREADS + tid);
                cp16(st + (FULLIT * THREADS + tid) * 4, t4 + FULLIT * THREADS + tid);
            }
        } else {
            // ragged last tile (dead for N=1M = 8192 full tiles); consumed only
            // after the __syncthreads preceding compute of this buffer.
            const int nflt = rows * C;
            for (int i = tid; i < nflt; i += THREADS) {
                sp[i] = pred[base + i];
                st[i] = tgt [base + i];
            }
        }
    };

    float acc = 0.0f;   // per-thread accumulator across tiles

    int tile = blockIdx.x;
    int buf  = 0;
    if (tile < ntiles)
        issue_tile(tile, 0);
    cp_commit();

    for (; tile < ntiles; tile += stride) {
        const int next = tile + stride;
        if (next < ntiles)
            issue_tile(next, buf ^ 1);
        cp_commit();          // every thread commits exactly one group per iter
        cp_wait1();           // all but newest group done -> current tile ready
        __syncthreads();      // everyone's copies visible

        // ---- compute from buffer `buf` ----
        const int rows = min(ROWS, nrows - tile * ROWS);
        if (tid < rows) {
            const float* __restrict__ pr = dynsm + buf * 2 * TILE_F + tid * C;
            const float* __restrict__ tr = pr + TILE_F;
            float l1 = 0.0f;
            float pmax = pr[0], tmax = tr[0];
            int   pidx = 0,     tidx = 0;
            #pragma unroll
            for (int c = 0; c < C; c++) {
                float a = pr[c];
                float b = tr[c];
                l1 += fabsf(a - b);
                if (a > pmax) { pmax = a; pidx = c; }  // strict > == jnp.argmax ties
                if (b > tmax) { tmax = b; tidx = c; }
            }
            acc += l1 * __ldg(&pen[pidx * C + tidx]);
        }
        __syncthreads();      // compute done before this buffer is overwritten
        buf ^= 1;
    }

    // ---- one reduction + one atomic per block ----
    #pragma unroll
    for (int off = 16; off > 0; off >>= 1)
        acc += __shfl_down_sync(0xffffffffu, acc, off);
    if ((tid & 31) == 0)
        s_warp[tid >> 5] = acc;
    __syncthreads();

    if (tid == 0) {
        float s = 0.0f;
        #pragma unroll
        for (int w = 0; w < THREADS / 32; w++)
            s += s_warp[w];

        atomicAdd(&g_acc, (double)s);
        __threadfence();
        unsigned done = atomicAdd(&g_count, 1u) + 1u;
        if (done == gridDim.x) {
            __threadfence();
            double v = atomicAdd(&g_acc, 0.0);
            *out = (float)(v / (double)nrows);
            g_acc = 0.0;          // self-reset for next graph replay
            __threadfence();
            g_count = 0u;
        }
    }
}

extern "C" void kernel_launch(void* const* d_in, const int* in_sizes, int n_in,
                              void* d_out, int out_size)
{
    int pen_i = -1;
    for (int i = 0; i < n_in; i++)
        if (in_sizes[i] == C * C) { pen_i = i; break; }
    int big[2], nb = 0;
    for (int i = 0; i < n_in && nb < 2; i++)
        if (i != pen_i) big[nb++] = i;

    const float* pred = (const float*)d_in[big[0]];
    const float* tgt  = (const float*)d_in[big[1]];
    const float* pen  = (const float*)d_in[pen_i];

    const int nrows = in_sizes[big[0]] / C;

    cudaFuncSetAttribute(l1pen_kernel,
                         cudaFuncAttributeMaxDynamicSharedMemorySize, SMEM_BYTES);

    l1pen_kernel<<<GRID, THREADS, SMEM_BYTES>>>(pred, tgt, pen, nrows,
                                                (float*)d_out);
}